// round 5
// baseline (speedup 1.0000x reference)
#include <cuda_runtime.h>
#include <cuda_bf16.h>
#include <cstdint>

// ---------------------------------------------------------------------------
// ChebConv K=3, N=100000, E=3200000, F_IN=F_OUT=128
//
// out = X@(W0-W1+W2) + Y1@(W1-4W2) + Y2@(2W2) + b
//   where S(h) = lap * norm ⊙ spmm(norm ⊙ h),  Y1 = S(X), Y2 = S(Y1)
//   (valid by linearity of S: Tx1 = Y1 - X, Tx2 = 2*Y2 - 4*Y1 + X)
//
// src/dst dtype (int32 vs int64) is SNIFFED at runtime on-device: int64 data
// viewed as int32 has all odd words == 0 (values < 2^31). All decoded indices
// are clamped, so the kernel is memory-safe under either layout.
// ---------------------------------------------------------------------------

#define NMAX 100000
#define EMAX 3200000
#define F 128

__device__ int   g_idx64;            // 1 if src/dst are int64, 0 if int32
__device__ int   g_deg[NMAX];
__device__ int   g_rowptr[NMAX + 1];
__device__ int   g_cursor[NMAX];
__device__ int   g_csr_src[EMAX];
__device__ float g_norm[NMAX];
__device__ float g_Y1[(size_t)NMAX * F];
__device__ float g_Y2[(size_t)NMAX * F];
__device__ float g_Wc[3 * F * F];    // A | B | C combined weights

__device__ __forceinline__ int clampi(int v, int n) {
    return v < 0 ? 0 : (v >= n ? n - 1 : v);
}

// ---------------------------------------------------------------------------
// packed f32x2 helpers
// ---------------------------------------------------------------------------
__device__ __forceinline__ unsigned long long pack2(float lo, float hi) {
    unsigned long long r;
    asm("mov.b64 %0, {%1, %2};" : "=l"(r) : "f"(lo), "f"(hi));
    return r;
}
__device__ __forceinline__ void unpack2(unsigned long long v, float& lo, float& hi) {
    asm("mov.b64 {%0, %1}, %2;" : "=f"(lo), "=f"(hi) : "l"(v));
}
#define FMA2(acc, a2, b2) \
    asm("fma.rn.f32x2 %0, %1, %2, %0;" : "+l"(acc) : "l"(a2), "l"(b2))

// ---------------------------------------------------------------------------
// dtype sniffer: reads first 64 int32 words of dst (within bounds for either
// dtype since E >= 64). int64 data => all odd words zero.
// ---------------------------------------------------------------------------
__global__ void k_sniff(const int* __restrict__ dst32, int E) {
    if (threadIdx.x == 0 && blockIdx.x == 0) {
        int m = E < 32 ? E : 32;     // inspect m index slots => 2m int32 words
        int odd_nonzero = 0;
        for (int i = 1; i < 2 * m; i += 2) odd_nonzero |= (dst32[i] != 0);
        g_idx64 = odd_nonzero ? 0 : 1;
    }
}

// ---------------------------------------------------------------------------
// CSR build (dtype-agnostic via g_idx64; little-endian low word = value)
// ---------------------------------------------------------------------------
__global__ void k_zero_deg(int n) {
    int i = blockIdx.x * blockDim.x + threadIdx.x;
    if (i < n) g_deg[i] = 0;
}

__global__ void k_hist(const int* __restrict__ dst, int E, int n) {
    int is64 = g_idx64;
    int i = blockIdx.x * blockDim.x + threadIdx.x;
    if (i < E) {
        int v = is64 ? dst[2 * i] : dst[i];
        atomicAdd(&g_deg[clampi(v, n)], 1);
    }
}

__global__ void k_norm(int n) {
    int i = blockIdx.x * blockDim.x + threadIdx.x;
    if (i < n) g_norm[i] = rsqrtf((float)g_deg[i]);   // deg=0 -> inf, matches deg**-0.5
}

__global__ void k_scan(int n) {
    __shared__ int sh_warp[32];
    __shared__ int sh_carry;
    int tid = threadIdx.x, lane = tid & 31, wid = tid >> 5;
    if (tid == 0) sh_carry = 0;
    __syncthreads();
    for (int base = 0; base < n; base += 1024) {
        int i = base + tid;
        int v = (i < n) ? g_deg[i] : 0;
        int x = v;
        #pragma unroll
        for (int d = 1; d < 32; d <<= 1) {
            int t = __shfl_up_sync(0xffffffffu, x, d);
            if (lane >= d) x += t;
        }
        if (lane == 31) sh_warp[wid] = x;
        __syncthreads();
        if (wid == 0) {
            int s = sh_warp[lane];
            #pragma unroll
            for (int d = 1; d < 32; d <<= 1) {
                int t = __shfl_up_sync(0xffffffffu, s, d);
                if (lane >= d) s += t;
            }
            sh_warp[lane] = s;
        }
        __syncthreads();
        int warp_off = (wid > 0) ? sh_warp[wid - 1] : 0;
        int total    = sh_warp[31];
        int excl     = sh_carry + warp_off + (x - v);
        if (i < n) { g_rowptr[i] = excl; g_cursor[i] = excl; }
        __syncthreads();
        if (tid == 0) sh_carry += total;
        __syncthreads();
    }
    if (threadIdx.x == 0) g_rowptr[n] = sh_carry;
}

__global__ void k_scatter(const int* __restrict__ src,
                          const int* __restrict__ dst, int E, int n) {
    int is64 = g_idx64;
    int i = blockIdx.x * blockDim.x + threadIdx.x;
    if (i < E) {
        int dv = is64 ? dst[2 * i] : dst[i];
        int sv = is64 ? src[2 * i] : src[i];
        int p = atomicAdd(&g_cursor[clampi(dv, n)], 1);
        if (p >= 0 && p < EMAX) g_csr_src[p] = clampi(sv, n);
    }
}

// ---------------------------------------------------------------------------
// SPMM: Y[v] = lap * norm[v] * sum_{u in row(v)} X[u] * norm[u]
// one warp per node, float4-per-lane row slice
// ---------------------------------------------------------------------------
__device__ __forceinline__ void spmm_body(const float4* __restrict__ X,
                                          float4* __restrict__ Y,
                                          float lap, int n) {
    int warp = (blockIdx.x * blockDim.x + threadIdx.x) >> 5;
    int lane = threadIdx.x & 31;
    if (warp >= n) return;
    int beg = g_rowptr[warp], end = g_rowptr[warp + 1];
    float4 acc = make_float4(0.f, 0.f, 0.f, 0.f);
    for (int e0 = beg; e0 < end; e0 += 32) {
        int e = e0 + lane;
        int u = 0; float nu = 0.f;
        if (e < end) { u = g_csr_src[e]; nu = g_norm[u]; }
        int cnt = min(32, end - e0);
        for (int j = 0; j < cnt; j++) {
            int   uj = __shfl_sync(0xffffffffu, u, j);
            float nj = __shfl_sync(0xffffffffu, nu, j);
            float4 x = X[(size_t)uj * (F / 4) + lane];
            acc.x = fmaf(x.x, nj, acc.x);
            acc.y = fmaf(x.y, nj, acc.y);
            acc.z = fmaf(x.z, nj, acc.z);
            acc.w = fmaf(x.w, nj, acc.w);
        }
    }
    float s = g_norm[warp] * lap;
    Y[(size_t)warp * (F / 4) + lane] =
        make_float4(acc.x * s, acc.y * s, acc.z * s, acc.w * s);
}

__global__ void k_spmm1(const float4* __restrict__ X,
                        const float* __restrict__ lambda_max, int n) {
    spmm_body(X, (float4*)g_Y1, 2.0f / lambda_max[0], n);
}

__global__ void k_spmm2(const float* __restrict__ lambda_max, int n) {
    spmm_body((const float4*)g_Y1, (float4*)g_Y2, 2.0f / lambda_max[0], n);
}

// ---------------------------------------------------------------------------
// Combined weights: A = W0 - W1 + W2, B = W1 - 4*W2, C = 2*W2
// ---------------------------------------------------------------------------
__global__ void k_wc(const float* __restrict__ W) {
    int i = blockIdx.x * blockDim.x + threadIdx.x;
    if (i < F * F) {
        float w0 = W[i], w1 = W[F * F + i], w2 = W[2 * F * F + i];
        g_Wc[i]             = w0 - w1 + w2;
        g_Wc[F * F + i]     = w1 - 4.0f * w2;
        g_Wc[2 * F * F + i] = 2.0f * w2;
    }
}

// ---------------------------------------------------------------------------
// GEMM: out[N,128] = [X | Y1 | Y2] (N,384) @ Wc (384,128) + b
// 128-row blocks, 256 threads, 8x8 per-thread tiles, f32x2 packed FMA.
// STATIC smem only: 16x132 A tile (8.4 KB) + 16x128 B slab (8 KB).
// Wc (192 KB) is L2-resident; each block re-stages its slabs from L2.
// ---------------------------------------------------------------------------
__global__ void __launch_bounds__(256)
k_gemm(const float* __restrict__ X, const float* __restrict__ bias,
       float* __restrict__ out, int n) {
    __shared__ float sA[16 * 132];   // [k][row], padded
    __shared__ float sB[16 * 128];   // [k][col]

    int tid = threadIdx.x;
    int tx = tid & 15, ty = tid >> 4;
    int blockRow = blockIdx.x * 128;

    unsigned long long acc[8][4];
    #pragma unroll
    for (int i = 0; i < 8; i++)
        #pragma unroll
        for (int j = 0; j < 4; j++) acc[i][j] = 0ull;

    for (int kt = 0; kt < 384; kt += 16) {
        const float* S = (kt < 128) ? X : (kt < 256) ? g_Y1 : g_Y2;
        int kb = kt & 127;
        __syncthreads();
        // stage A tile: 128 rows x 16 k, transposed into [k][row]
        #pragma unroll
        for (int p = 0; p < 2; p++) {
            int r  = (tid >> 2) + (p << 6);
            int gr = blockRow + r;
            if (gr >= n) gr = n - 1;
            const float4 v = *(const float4*)(S + (size_t)gr * F + kb + ((tid & 3) << 2));
            int kq = (tid & 3) << 2;
            sA[(kq + 0) * 132 + r] = v.x;
            sA[(kq + 1) * 132 + r] = v.y;
            sA[(kq + 2) * 132 + r] = v.z;
            sA[(kq + 3) * 132 + r] = v.w;
        }
        // stage B slab: 16 k x 128 cols (from L2-resident g_Wc)
        {
            const float4* s = (const float4*)(g_Wc + kt * 128);
            float4* d = (float4*)sB;
            #pragma unroll
            for (int p = 0; p < 2; p++) d[tid + p * 256] = s[tid + p * 256];
        }
        __syncthreads();
        #pragma unroll
        for (int kk = 0; kk < 16; kk++) {
            const float4 a0 = *(const float4*)&sA[kk * 132 + ty * 8];
            const float4 a1 = *(const float4*)&sA[kk * 132 + ty * 8 + 4];
            const float4 b0 = *(const float4*)&sB[kk * 128 + tx * 8];
            const float4 b1 = *(const float4*)&sB[kk * 128 + tx * 8 + 4];
            unsigned long long B0 = pack2(b0.x, b0.y), B1 = pack2(b0.z, b0.w);
            unsigned long long B2 = pack2(b1.x, b1.y), B3 = pack2(b1.z, b1.w);
            float a[8] = {a0.x, a0.y, a0.z, a0.w, a1.x, a1.y, a1.z, a1.w};
            #pragma unroll
            for (int i = 0; i < 8; i++) {
                unsigned long long a2 = pack2(a[i], a[i]);
                FMA2(acc[i][0], a2, B0);
                FMA2(acc[i][1], a2, B1);
                FMA2(acc[i][2], a2, B2);
                FMA2(acc[i][3], a2, B3);
            }
        }
    }

    float bj[8];
    #pragma unroll
    for (int j = 0; j < 8; j++) bj[j] = bias[tx * 8 + j];

    #pragma unroll
    for (int i = 0; i < 8; i++) {
        int gr = blockRow + ty * 8 + i;
        if (gr < n) {
            float o[8];
            #pragma unroll
            for (int j = 0; j < 4; j++) unpack2(acc[i][j], o[2 * j], o[2 * j + 1]);
            #pragma unroll
            for (int j = 0; j < 8; j++) o[j] += bj[j];
            float4* dp = (float4*)(out + (size_t)gr * F + tx * 8);
            dp[0] = make_float4(o[0], o[1], o[2], o[3]);
            dp[1] = make_float4(o[4], o[5], o[6], o[7]);
        }
    }
}

// ---------------------------------------------------------------------------
// launch — stream-ordered kernel launches ONLY (graph-capture safe)
// ---------------------------------------------------------------------------
extern "C" void kernel_launch(void* const* d_in, const int* in_sizes, int n_in,
                              void* d_out, int out_size) {
    const float* feat = (const float*)d_in[0];
    const int*   src  = (const int*)d_in[1];     // int32 view; dtype sniffed
    const int*   dst  = (const int*)d_in[2];
    const float* W    = (const float*)d_in[3];
    const float* b    = (const float*)d_in[4];
    const float* lmax = (const float*)d_in[5];
    float*       out  = (float*)d_out;

    int N = in_sizes[0] / F;
    int E = in_sizes[1];

    int nb  = (N + 255) / 256;
    int eb  = (E + 255) / 256;
    int sb  = (N + 7) / 8;       // 8 warps/block, warp per node
    int gb  = (N + 127) / 128;

    k_sniff<<<1, 32>>>(dst, E);
    k_zero_deg<<<nb, 256>>>(N);
    k_hist<<<eb, 256>>>(dst, E, N);
    k_norm<<<nb, 256>>>(N);
    k_scan<<<1, 1024>>>(N);
    k_scatter<<<eb, 256>>>(src, dst, E, N);
    k_wc<<<(F * F + 255) / 256, 256>>>(W);

    k_spmm1<<<sb, 256>>>((const float4*)feat, lmax, N);
    k_spmm2<<<sb, 256>>>(lmax, N);

    k_gemm<<<gb, 256>>>(feat, b, out, N);

    (void)n_in; (void)out_size;
}

// round 6
// speedup vs baseline: 1.0200x; 1.0200x over previous
#include <cuda_runtime.h>
#include <cuda_fp16.h>
#include <cuda_bf16.h>
#include <cstdint>

// ---------------------------------------------------------------------------
// ChebConv K=3, N=100000, E=3200000, F_IN=F_OUT=128
//
// out = X@(W0-W1+W2) + Y1@(W1-4W2) + Y2@(2W2) + b
//   where S(h) = lap * norm ⊙ spmm(norm ⊙ h),  Y1 = S(X), Y2 = S(Y1)
//
// This round: SPMM gathers read fp16 rows (256B instead of 512B per edge,
// fp32 accumulation) — halves the L2-bound gather traffic. GEMM stays fp32.
// Launches packed so ncu's skip window lands on k_spmm1.
// ---------------------------------------------------------------------------

#define NMAX 100000
#define EMAX 3200000
#define F 128

__device__ int    g_idx64;            // 1 if src/dst are int64, 0 if int32
__device__ int    g_deg[NMAX];
__device__ int    g_rowptr[NMAX + 1];
__device__ int    g_cursor[NMAX];
__device__ int    g_csr_src[EMAX];
__device__ float  g_norm[NMAX];
__device__ __half g_Xh[(size_t)NMAX * F];    // half copy of feat
__device__ __half g_Y1h[(size_t)NMAX * F];   // half copy of Y1
__device__ float  g_Y1[(size_t)NMAX * F];
__device__ float  g_Y2[(size_t)NMAX * F];
__device__ float  g_Wc[3 * F * F];           // A | B | C combined weights

__device__ __forceinline__ int clampi(int v, int n) {
    return v < 0 ? 0 : (v >= n ? n - 1 : v);
}

// ---------------------------------------------------------------------------
// packed f32x2 helpers
// ---------------------------------------------------------------------------
__device__ __forceinline__ unsigned long long pack2(float lo, float hi) {
    unsigned long long r;
    asm("mov.b64 %0, {%1, %2};" : "=l"(r) : "f"(lo), "f"(hi));
    return r;
}
__device__ __forceinline__ void unpack2(unsigned long long v, float& lo, float& hi) {
    asm("mov.b64 {%0, %1}, %2;" : "=f"(lo), "=f"(hi) : "l"(v));
}
#define FMA2(acc, a2, b2) \
    asm("fma.rn.f32x2 %0, %1, %2, %0;" : "+l"(acc) : "l"(a2), "l"(b2))

// ---------------------------------------------------------------------------
// init: zero degree array + sniff index dtype (int64 viewed as int32 has all
// odd words zero since values < 2^31)
// ---------------------------------------------------------------------------
__global__ void k_init(const int* __restrict__ dst32, int E, int n) {
    int i = blockIdx.x * blockDim.x + threadIdx.x;
    if (i < n) g_deg[i] = 0;
    if (i == 0) {
        int m = E < 32 ? E : 32;
        int odd_nonzero = 0;
        for (int k = 1; k < 2 * m; k += 2) odd_nonzero |= (dst32[k] != 0);
        g_idx64 = odd_nonzero ? 0 : 1;
    }
}

__global__ void k_hist(const int* __restrict__ dst, int E, int n) {
    int is64 = g_idx64;
    int i = blockIdx.x * blockDim.x + threadIdx.x;
    if (i < E) {
        int v = is64 ? dst[2 * i] : dst[i];
        atomicAdd(&g_deg[clampi(v, n)], 1);
    }
}

// scan (exclusive prefix over degrees) + inline norm computation
__global__ void k_scan(int n) {
    __shared__ int sh_warp[32];
    __shared__ int sh_carry;
    int tid = threadIdx.x, lane = tid & 31, wid = tid >> 5;
    if (tid == 0) sh_carry = 0;
    __syncthreads();
    for (int base = 0; base < n; base += 1024) {
        int i = base + tid;
        int v = (i < n) ? g_deg[i] : 0;
        if (i < n) g_norm[i] = rsqrtf((float)v);
        int x = v;
        #pragma unroll
        for (int d = 1; d < 32; d <<= 1) {
            int t = __shfl_up_sync(0xffffffffu, x, d);
            if (lane >= d) x += t;
        }
        if (lane == 31) sh_warp[wid] = x;
        __syncthreads();
        if (wid == 0) {
            int s = sh_warp[lane];
            #pragma unroll
            for (int d = 1; d < 32; d <<= 1) {
                int t = __shfl_up_sync(0xffffffffu, s, d);
                if (lane >= d) s += t;
            }
            sh_warp[lane] = s;
        }
        __syncthreads();
        int warp_off = (wid > 0) ? sh_warp[wid - 1] : 0;
        int total    = sh_warp[31];
        int excl     = sh_carry + warp_off + (x - v);
        if (i < n) { g_rowptr[i] = excl; g_cursor[i] = excl; }
        __syncthreads();
        if (tid == 0) sh_carry += total;
        __syncthreads();
    }
    if (threadIdx.x == 0) g_rowptr[n] = sh_carry;
}

__global__ void k_scatter(const int* __restrict__ src,
                          const int* __restrict__ dst, int E, int n) {
    int is64 = g_idx64;
    int i = blockIdx.x * blockDim.x + threadIdx.x;
    if (i < E) {
        int dv = is64 ? dst[2 * i] : dst[i];
        int sv = is64 ? src[2 * i] : src[i];
        int p = atomicAdd(&g_cursor[clampi(dv, n)], 1);
        if (p >= 0 && p < EMAX) g_csr_src[p] = clampi(sv, n);
    }
}

// ---------------------------------------------------------------------------
// prep: feat -> half copy (vectorized), and combined weights
// ---------------------------------------------------------------------------
__global__ void k_prep(const float4* __restrict__ feat4,
                       const float* __restrict__ W, int n4) {
    int i = blockIdx.x * blockDim.x + threadIdx.x;
    if (i < n4) {
        float4 v = feat4[i];
        __half2 a = __floats2half2_rn(v.x, v.y);
        __half2 b = __floats2half2_rn(v.z, v.w);
        uint2 o;
        o.x = *reinterpret_cast<unsigned int*>(&a);
        o.y = *reinterpret_cast<unsigned int*>(&b);
        reinterpret_cast<uint2*>(g_Xh)[i] = o;
    }
    if (i < F * F) {
        float w0 = W[i], w1 = W[F * F + i], w2 = W[2 * F * F + i];
        g_Wc[i]             = w0 - w1 + w2;
        g_Wc[F * F + i]     = w1 - 4.0f * w2;
        g_Wc[2 * F * F + i] = 2.0f * w2;
    }
}

// ---------------------------------------------------------------------------
// SPMM (half gather, fp32 accumulate):
//   Y[v] = lap * norm[v] * sum_{u in row(v)} Xh[u] * norm[u]
// one warp per node; lane holds 4 features (8B half4 load per edge per lane)
// ---------------------------------------------------------------------------
__device__ __forceinline__ void spmm_body_h(const __half* __restrict__ Xh,
                                            float4* __restrict__ Y,
                                            __half* __restrict__ Yh,  // may be null
                                            float lap, int n) {
    int warp = (blockIdx.x * blockDim.x + threadIdx.x) >> 5;
    int lane = threadIdx.x & 31;
    if (warp >= n) return;
    int beg = g_rowptr[warp], end = g_rowptr[warp + 1];
    float4 acc = make_float4(0.f, 0.f, 0.f, 0.f);
    const uint2* Xv = reinterpret_cast<const uint2*>(Xh);
    for (int e0 = beg; e0 < end; e0 += 32) {
        int e = e0 + lane;
        int u = 0; float nu = 0.f;
        if (e < end) { u = g_csr_src[e]; nu = g_norm[u]; }
        int cnt = min(32, end - e0);
        for (int j = 0; j < cnt; j++) {
            int   uj = __shfl_sync(0xffffffffu, u, j);
            float nj = __shfl_sync(0xffffffffu, nu, j);
            uint2 xv = Xv[(size_t)uj * 32 + lane];
            __half2 h0 = *reinterpret_cast<__half2*>(&xv.x);
            __half2 h1 = *reinterpret_cast<__half2*>(&xv.y);
            float2 f0 = __half22float2(h0);
            float2 f1 = __half22float2(h1);
            acc.x = fmaf(f0.x, nj, acc.x);
            acc.y = fmaf(f0.y, nj, acc.y);
            acc.z = fmaf(f1.x, nj, acc.z);
            acc.w = fmaf(f1.y, nj, acc.w);
        }
    }
    float s = g_norm[warp] * lap;
    float4 o = make_float4(acc.x * s, acc.y * s, acc.z * s, acc.w * s);
    Y[(size_t)warp * (F / 4) + lane] = o;
    if (Yh) {
        __half2 a = __floats2half2_rn(o.x, o.y);
        __half2 b = __floats2half2_rn(o.z, o.w);
        uint2 ov;
        ov.x = *reinterpret_cast<unsigned int*>(&a);
        ov.y = *reinterpret_cast<unsigned int*>(&b);
        reinterpret_cast<uint2*>(Yh)[(size_t)warp * 32 + lane] = ov;
    }
}

__global__ void k_spmm1(const float* __restrict__ lambda_max, int n) {
    spmm_body_h(g_Xh, (float4*)g_Y1, g_Y1h, 2.0f / lambda_max[0], n);
}

__global__ void k_spmm2(const float* __restrict__ lambda_max, int n) {
    spmm_body_h(g_Y1h, (float4*)g_Y2, ((__half*)0), 2.0f / lambda_max[0], n);
}

// ---------------------------------------------------------------------------
// GEMM: out[N,128] = [X | Y1 | Y2] (N,384) @ Wc (384,128) + b   (all fp32)
// 128-row blocks, 256 threads, 8x8 per-thread tiles, f32x2 packed FMA.
// STATIC smem: 16x132 A tile + 16x128 B slab; Wc stays L2-resident.
// ---------------------------------------------------------------------------
__global__ void __launch_bounds__(256)
k_gemm(const float* __restrict__ X, const float* __restrict__ bias,
       float* __restrict__ out, int n) {
    __shared__ float sA[16 * 132];   // [k][row], padded
    __shared__ float sB[16 * 128];   // [k][col]

    int tid = threadIdx.x;
    int tx = tid & 15, ty = tid >> 4;
    int blockRow = blockIdx.x * 128;

    unsigned long long acc[8][4];
    #pragma unroll
    for (int i = 0; i < 8; i++)
        #pragma unroll
        for (int j = 0; j < 4; j++) acc[i][j] = 0ull;

    for (int kt = 0; kt < 384; kt += 16) {
        const float* S = (kt < 128) ? X : (kt < 256) ? g_Y1 : g_Y2;
        int kb = kt & 127;
        __syncthreads();
        // stage A tile: 128 rows x 16 k, transposed into [k][row]
        #pragma unroll
        for (int p = 0; p < 2; p++) {
            int r  = (tid >> 2) + (p << 6);
            int gr = blockRow + r;
            if (gr >= n) gr = n - 1;
            const float4 v = *(const float4*)(S + (size_t)gr * F + kb + ((tid & 3) << 2));
            int kq = (tid & 3) << 2;
            sA[(kq + 0) * 132 + r] = v.x;
            sA[(kq + 1) * 132 + r] = v.y;
            sA[(kq + 2) * 132 + r] = v.z;
            sA[(kq + 3) * 132 + r] = v.w;
        }
        // stage B slab: 16 k x 128 cols (from L2-resident g_Wc)
        {
            const float4* s = (const float4*)(g_Wc + kt * 128);
            float4* d = (float4*)sB;
            #pragma unroll
            for (int p = 0; p < 2; p++) d[tid + p * 256] = s[tid + p * 256];
        }
        __syncthreads();
        #pragma unroll
        for (int kk = 0; kk < 16; kk++) {
            const float4 a0 = *(const float4*)&sA[kk * 132 + ty * 8];
            const float4 a1 = *(const float4*)&sA[kk * 132 + ty * 8 + 4];
            const float4 b0 = *(const float4*)&sB[kk * 128 + tx * 8];
            const float4 b1 = *(const float4*)&sB[kk * 128 + tx * 8 + 4];
            unsigned long long B0 = pack2(b0.x, b0.y), B1 = pack2(b0.z, b0.w);
            unsigned long long B2 = pack2(b1.x, b1.y), B3 = pack2(b1.z, b1.w);
            float a[8] = {a0.x, a0.y, a0.z, a0.w, a1.x, a1.y, a1.z, a1.w};
            #pragma unroll
            for (int i = 0; i < 8; i++) {
                unsigned long long a2 = pack2(a[i], a[i]);
                FMA2(acc[i][0], a2, B0);
                FMA2(acc[i][1], a2, B1);
                FMA2(acc[i][2], a2, B2);
                FMA2(acc[i][3], a2, B3);
            }
        }
    }

    float bj[8];
    #pragma unroll
    for (int j = 0; j < 8; j++) bj[j] = bias[tx * 8 + j];

    #pragma unroll
    for (int i = 0; i < 8; i++) {
        int gr = blockRow + ty * 8 + i;
        if (gr < n) {
            float o[8];
            #pragma unroll
            for (int j = 0; j < 4; j++) unpack2(acc[i][j], o[2 * j], o[2 * j + 1]);
            #pragma unroll
            for (int j = 0; j < 8; j++) o[j] += bj[j];
            float4* dp = (float4*)(out + (size_t)gr * F + tx * 8);
            dp[0] = make_float4(o[0], o[1], o[2], o[3]);
            dp[1] = make_float4(o[4], o[5], o[6], o[7]);
        }
    }
}

// ---------------------------------------------------------------------------
// launch — stream-ordered kernel launches ONLY (graph-capture safe)
// launch order puts k_spmm1 at position 6 for the ncu -s 5 -c 1 window
// ---------------------------------------------------------------------------
extern "C" void kernel_launch(void* const* d_in, const int* in_sizes, int n_in,
                              void* d_out, int out_size) {
    const float* feat = (const float*)d_in[0];
    const int*   src  = (const int*)d_in[1];     // int32 view; dtype sniffed
    const int*   dst  = (const int*)d_in[2];
    const float* W    = (const float*)d_in[3];
    const float* b    = (const float*)d_in[4];
    const float* lmax = (const float*)d_in[5];
    float*       out  = (float*)d_out;

    int N = in_sizes[0] / F;
    int E = in_sizes[1];

    int nb  = (N + 255) / 256;
    int eb  = (E + 255) / 256;
    int sb  = (N + 7) / 8;             // 8 warps/block, warp per node
    int gb  = (N + 127) / 128;
    int n4  = (N * F) / 4;
    int pb  = (n4 + 255) / 256;

    k_init<<<nb, 256>>>(dst, E, N);                      // 1
    k_hist<<<eb, 256>>>(dst, E, N);                      // 2
    k_scan<<<1, 1024>>>(N);                              // 3 (+norm)
    k_scatter<<<eb, 256>>>(src, dst, E, N);              // 4
    k_prep<<<pb, 256>>>((const float4*)feat, W, n4);     // 5 (Xh + Wc)
    k_spmm1<<<sb, 256>>>(lmax, N);                       // 6  <- ncu window
    k_spmm2<<<sb, 256>>>(lmax, N);                       // 7
    k_gemm<<<gb, 256>>>(feat, b, out, N);                // 8

    (void)n_in; (void)out_size;
}

// round 7
// speedup vs baseline: 1.5766x; 1.5457x over previous
#include <cuda_runtime.h>
#include <cuda_fp16.h>
#include <cuda_bf16.h>
#include <cstdint>

// ---------------------------------------------------------------------------
// ChebConv K=3, N=100000, E=3200000, F_IN=F_OUT=128
//
// out = X@(W0-W1+W2) + Y1@(W1-4W2) + Y2@(2W2) + b
//   where S(h) = lap * norm ⊙ spmm(norm ⊙ h),  Y1 = S(X), Y2 = S(Y1)
//
// Round 7: SPMM inner loop unrolled x4 (4 outstanding gathers/warp) over
// norm-prescaled fp16 rows; GEMM rewritten as tf32 mma.sync warp-tile.
// ---------------------------------------------------------------------------

#define NMAX 100000
#define EMAX 3200000
#define F 128

__device__ int    g_idx64;            // 1 if src/dst are int64, 0 if int32
__device__ int    g_deg[NMAX];
__device__ int    g_rowptr[NMAX + 1];
__device__ int    g_cursor[NMAX];
__device__ int    g_csr_src[EMAX];
__device__ float  g_norm[NMAX];
__device__ __half g_Xh[(size_t)NMAX * F];    // half(norm[u] * X[u])
__device__ __half g_Y1h[(size_t)NMAX * F];   // half(norm[u] * Y1[u])
__device__ float  g_Y1[(size_t)NMAX * F];
__device__ float  g_Y2[(size_t)NMAX * F];
__device__ float  g_Wc[3 * F * F];           // combined weights, tf32-rounded

__device__ __forceinline__ int clampi(int v, int n) {
    return v < 0 ? 0 : (v >= n ? n - 1 : v);
}

__device__ __forceinline__ float to_tf32(float x) {
    unsigned int u;
    asm("cvt.rna.tf32.f32 %0, %1;" : "=r"(u) : "f"(x));
    return __uint_as_float(u);
}

__device__ __forceinline__ void mma_tf32(float* d, const unsigned int* a,
                                         const unsigned int* b) {
    asm volatile(
        "mma.sync.aligned.m16n8k8.row.col.f32.tf32.tf32.f32 "
        "{%0,%1,%2,%3}, {%4,%5,%6,%7}, {%8,%9}, {%0,%1,%2,%3};"
        : "+f"(d[0]), "+f"(d[1]), "+f"(d[2]), "+f"(d[3])
        : "r"(a[0]), "r"(a[1]), "r"(a[2]), "r"(a[3]), "r"(b[0]), "r"(b[1]));
}

// ---------------------------------------------------------------------------
// init: zero degree array + sniff index dtype (int64 viewed as int32 has all
// odd words zero since values < 2^31)
// ---------------------------------------------------------------------------
__global__ void k_init(const int* __restrict__ dst32, int E, int n) {
    int i = blockIdx.x * blockDim.x + threadIdx.x;
    if (i < n) g_deg[i] = 0;
    if (i == 0) {
        int m = E < 32 ? E : 32;
        int odd_nonzero = 0;
        for (int k = 1; k < 2 * m; k += 2) odd_nonzero |= (dst32[k] != 0);
        g_idx64 = odd_nonzero ? 0 : 1;
    }
}

__global__ void k_hist(const int* __restrict__ dst, int E, int n) {
    int is64 = g_idx64;
    int i = blockIdx.x * blockDim.x + threadIdx.x;
    if (i < E) {
        int v = is64 ? dst[2 * i] : dst[i];
        atomicAdd(&g_deg[clampi(v, n)], 1);
    }
}

// scan (exclusive prefix over degrees) + inline norm computation
__global__ void k_scan(int n) {
    __shared__ int sh_warp[32];
    __shared__ int sh_carry;
    int tid = threadIdx.x, lane = tid & 31, wid = tid >> 5;
    if (tid == 0) sh_carry = 0;
    __syncthreads();
    for (int base = 0; base < n; base += 1024) {
        int i = base + tid;
        int v = (i < n) ? g_deg[i] : 0;
        if (i < n) g_norm[i] = rsqrtf((float)v);
        int x = v;
        #pragma unroll
        for (int d = 1; d < 32; d <<= 1) {
            int t = __shfl_up_sync(0xffffffffu, x, d);
            if (lane >= d) x += t;
        }
        if (lane == 31) sh_warp[wid] = x;
        __syncthreads();
        if (wid == 0) {
            int s = sh_warp[lane];
            #pragma unroll
            for (int d = 1; d < 32; d <<= 1) {
                int t = __shfl_up_sync(0xffffffffu, s, d);
                if (lane >= d) s += t;
            }
            sh_warp[lane] = s;
        }
        __syncthreads();
        int warp_off = (wid > 0) ? sh_warp[wid - 1] : 0;
        int total    = sh_warp[31];
        int excl     = sh_carry + warp_off + (x - v);
        if (i < n) { g_rowptr[i] = excl; g_cursor[i] = excl; }
        __syncthreads();
        if (tid == 0) sh_carry += total;
        __syncthreads();
    }
    if (threadIdx.x == 0) g_rowptr[n] = sh_carry;
}

__global__ void k_scatter(const int* __restrict__ src,
                          const int* __restrict__ dst, int E, int n) {
    int is64 = g_idx64;
    int i = blockIdx.x * blockDim.x + threadIdx.x;
    if (i < E) {
        int dv = is64 ? dst[2 * i] : dst[i];
        int sv = is64 ? src[2 * i] : src[i];
        int p = atomicAdd(&g_cursor[clampi(dv, n)], 1);
        if (p >= 0 && p < EMAX) g_csr_src[p] = clampi(sv, n);
    }
}

// ---------------------------------------------------------------------------
// prep: Xh = half(norm[row] * X)  (gather-ready), Wc combined + tf32-rounded
// must run AFTER k_scan (needs g_norm)
// ---------------------------------------------------------------------------
__global__ void k_prep(const float4* __restrict__ feat4,
                       const float* __restrict__ W, int n4) {
    int i = blockIdx.x * blockDim.x + threadIdx.x;
    if (i < n4) {
        int row = i >> 5;                     // 32 float4 per 128-float row
        float nr = g_norm[row];
        float4 v = feat4[i];
        __half2 a = __floats2half2_rn(v.x * nr, v.y * nr);
        __half2 b = __floats2half2_rn(v.z * nr, v.w * nr);
        uint2 o;
        o.x = *reinterpret_cast<unsigned int*>(&a);
        o.y = *reinterpret_cast<unsigned int*>(&b);
        reinterpret_cast<uint2*>(g_Xh)[i] = o;
    }
    if (i < F * F) {
        float w0 = W[i], w1 = W[F * F + i], w2 = W[2 * F * F + i];
        g_Wc[i]             = to_tf32(w0 - w1 + w2);
        g_Wc[F * F + i]     = to_tf32(w1 - 4.0f * w2);
        g_Wc[2 * F * F + i] = to_tf32(2.0f * w2);
    }
}

// ---------------------------------------------------------------------------
// SPMM over prescaled half rows: Y[v] = lap*norm[v] * sum_u Xs[u]
// one warp per node; inner loop unrolled x4 => 4 outstanding gathers/warp
// ---------------------------------------------------------------------------
__device__ __forceinline__ void acc_half4(float4& acc, uint2 xv) {
    __half2 h0 = *reinterpret_cast<__half2*>(&xv.x);
    __half2 h1 = *reinterpret_cast<__half2*>(&xv.y);
    float2 f0 = __half22float2(h0);
    float2 f1 = __half22float2(h1);
    acc.x += f0.x; acc.y += f0.y; acc.z += f1.x; acc.w += f1.y;
}

__device__ __forceinline__ void spmm_body(const uint2* __restrict__ Xv,
                                          float4* __restrict__ Y,
                                          uint2* __restrict__ Yh,   // null ok
                                          float lap, int n) {
    int warp = (blockIdx.x * blockDim.x + threadIdx.x) >> 5;
    int lane = threadIdx.x & 31;
    if (warp >= n) return;
    int beg = g_rowptr[warp], end = g_rowptr[warp + 1];
    float4 acc = make_float4(0.f, 0.f, 0.f, 0.f);
    for (int e0 = beg; e0 < end; e0 += 32) {
        int e = e0 + lane;
        int u = (e < end) ? g_csr_src[e] : 0;
        int cnt = min(32, end - e0);
        int j = 0;
        for (; j + 4 <= cnt; j += 4) {
            int u0 = __shfl_sync(0xffffffffu, u, j);
            int u1 = __shfl_sync(0xffffffffu, u, j + 1);
            int u2 = __shfl_sync(0xffffffffu, u, j + 2);
            int u3 = __shfl_sync(0xffffffffu, u, j + 3);
            uint2 x0 = Xv[(size_t)u0 * 32 + lane];
            uint2 x1 = Xv[(size_t)u1 * 32 + lane];
            uint2 x2 = Xv[(size_t)u2 * 32 + lane];
            uint2 x3 = Xv[(size_t)u3 * 32 + lane];
            acc_half4(acc, x0);
            acc_half4(acc, x1);
            acc_half4(acc, x2);
            acc_half4(acc, x3);
        }
        for (; j < cnt; j++) {
            int uj = __shfl_sync(0xffffffffu, u, j);
            uint2 xj = Xv[(size_t)uj * 32 + lane];
            acc_half4(acc, xj);
        }
    }
    float nv = g_norm[warp];
    float s = nv * lap;
    float4 o = make_float4(acc.x * s, acc.y * s, acc.z * s, acc.w * s);
    Y[(size_t)warp * (F / 4) + lane] = o;
    if (Yh) {
        __half2 a = __floats2half2_rn(o.x * nv, o.y * nv);
        __half2 b = __floats2half2_rn(o.z * nv, o.w * nv);
        uint2 ov;
        ov.x = *reinterpret_cast<unsigned int*>(&a);
        ov.y = *reinterpret_cast<unsigned int*>(&b);
        Yh[(size_t)warp * 32 + lane] = ov;
    }
}

__global__ void k_spmm1(const float* __restrict__ lambda_max, int n) {
    spmm_body(reinterpret_cast<const uint2*>(g_Xh), (float4*)g_Y1,
              reinterpret_cast<uint2*>(g_Y1h), 2.0f / lambda_max[0], n);
}

__global__ void k_spmm2(const float* __restrict__ lambda_max, int n) {
    spmm_body(reinterpret_cast<const uint2*>(g_Y1h), (float4*)g_Y2,
              (uint2*)0, 2.0f / lambda_max[0], n);
}

// ---------------------------------------------------------------------------
// GEMM (tf32 mma): out[N,128] = [X | Y1 | Y2](N,384) @ Wc(384,128) + b
// block = 128 rows x 128 cols, 256 threads (8 warps), warp tile 32x64.
// smem: sA[128][36] (A chunk, tf32), sB[32][136] (W chunk) — frag loads are
// provably bank-conflict-free (bank == lane for A, 8*(lane%4)+lane/4 for B).
// ---------------------------------------------------------------------------
__global__ void __launch_bounds__(256)
k_gemm(const float* __restrict__ X, const float* __restrict__ bias,
       float* __restrict__ out, int n) {
    __shared__ float sA[128 * 36];
    __shared__ float sB[32 * 136];

    int tid  = threadIdx.x;
    int lane = tid & 31;
    int w    = tid >> 5;
    int wm   = w & 3;        // 32-row group
    int wn   = w >> 2;       // 64-col group
    int blockRow = blockIdx.x * 128;

    float acc[2][8][4];
    #pragma unroll
    for (int mt = 0; mt < 2; mt++)
        #pragma unroll
        for (int nt = 0; nt < 8; nt++)
            #pragma unroll
            for (int r = 0; r < 4; r++) acc[mt][nt][r] = 0.f;

    for (int kt = 0; kt < 12; kt++) {
        const float* S = (kt < 4) ? X : (kt < 8) ? g_Y1 : g_Y2;
        int kb = (kt * 32) & 127;
        __syncthreads();
        // stage A: 128 rows x 32 k (tf32-rounded)
        #pragma unroll
        for (int p = 0; p < 4; p++) {
            int idx = tid + p * 256;          // 0..1023
            int r   = idx >> 3;
            int kq  = (idx & 7) << 2;
            int gr  = blockRow + r; if (gr >= n) gr = n - 1;
            float4 v = *(const float4*)(S + (size_t)gr * F + kb + kq);
            v.x = to_tf32(v.x); v.y = to_tf32(v.y);
            v.z = to_tf32(v.z); v.w = to_tf32(v.w);
            *(float4*)&sA[r * 36 + kq] = v;
        }
        // stage B: 32 k x 128 cols (already tf32)
        #pragma unroll
        for (int p = 0; p < 4; p++) {
            int idx = tid + p * 256;          // 0..1023
            int k   = idx >> 5;
            int c4  = (idx & 31) << 2;
            float4 v = *(const float4*)(g_Wc + (size_t)(kt * 32 + k) * F + c4);
            *(float4*)&sB[k * 136 + c4] = v;
        }
        __syncthreads();
        #pragma unroll
        for (int s = 0; s < 4; s++) {
            int k0 = s * 8 + (lane & 3);
            unsigned int a[2][4];
            #pragma unroll
            for (int mt = 0; mt < 2; mt++) {
                int r = wm * 32 + mt * 16 + (lane >> 2);
                a[mt][0] = __float_as_uint(sA[r * 36 + k0]);
                a[mt][1] = __float_as_uint(sA[(r + 8) * 36 + k0]);
                a[mt][2] = __float_as_uint(sA[r * 36 + k0 + 4]);
                a[mt][3] = __float_as_uint(sA[(r + 8) * 36 + k0 + 4]);
            }
            unsigned int b[8][2];
            #pragma unroll
            for (int nt = 0; nt < 8; nt++) {
                int c = wn * 64 + nt * 8 + (lane >> 2);
                b[nt][0] = __float_as_uint(sB[k0 * 136 + c]);
                b[nt][1] = __float_as_uint(sB[(k0 + 4) * 136 + c]);
            }
            #pragma unroll
            for (int mt = 0; mt < 2; mt++)
                #pragma unroll
                for (int nt = 0; nt < 8; nt++)
                    mma_tf32(acc[mt][nt], a[mt], b[nt]);
        }
    }

    #pragma unroll
    for (int mt = 0; mt < 2; mt++) {
        #pragma unroll
        for (int nt = 0; nt < 8; nt++) {
            int r = blockRow + wm * 32 + mt * 16 + (lane >> 2);
            int c = wn * 64 + nt * 8 + ((lane & 3) << 1);
            float2 bb = *(const float2*)(bias + c);
            if (r < n)
                *(float2*)(out + (size_t)r * F + c) =
                    make_float2(acc[mt][nt][0] + bb.x, acc[mt][nt][1] + bb.y);
            if (r + 8 < n)
                *(float2*)(out + (size_t)(r + 8) * F + c) =
                    make_float2(acc[mt][nt][2] + bb.x, acc[mt][nt][3] + bb.y);
        }
    }
}

// ---------------------------------------------------------------------------
// launch — stream-ordered kernel launches ONLY (graph-capture safe)
// ---------------------------------------------------------------------------
extern "C" void kernel_launch(void* const* d_in, const int* in_sizes, int n_in,
                              void* d_out, int out_size) {
    const float* feat = (const float*)d_in[0];
    const int*   src  = (const int*)d_in[1];     // int32 view; dtype sniffed
    const int*   dst  = (const int*)d_in[2];
    const float* W    = (const float*)d_in[3];
    const float* b    = (const float*)d_in[4];
    const float* lmax = (const float*)d_in[5];
    float*       out  = (float*)d_out;

    int N = in_sizes[0] / F;
    int E = in_sizes[1];

    int nb  = (N + 255) / 256;
    int eb  = (E + 255) / 256;
    int sb  = (N + 7) / 8;             // 8 warps/block, warp per node
    int gb  = (N + 127) / 128;
    int n4  = (N * F) / 4;
    int pb  = (n4 + 255) / 256;

    k_init<<<nb, 256>>>(dst, E, N);
    k_hist<<<eb, 256>>>(dst, E, N);
    k_scan<<<1, 1024>>>(N);
    k_scatter<<<eb, 256>>>(src, dst, E, N);
    k_prep<<<pb, 256>>>((const float4*)feat, W, n4);
    k_spmm1<<<sb, 256>>>(lmax, N);
    k_spmm2<<<sb, 256>>>(lmax, N);
    k_gemm<<<gb, 256>>>(feat, b, out, N);

    (void)n_in; (void)out_size;
}